// round 2
// baseline (speedup 1.0000x reference)
#include <cuda_runtime.h>
#include <cuda_bf16.h>

#define N_NODES 8192
#define IN_DIM  256
#define OUT_DIM 128
#define NEG_SLOPE 0.2f

#define BI 16
#define BJ 64
#define TPB 128

// Scratch (no allocations allowed): Wh [8192x128] fp32, score vectors.
__device__ float g_Wh[N_NODES * OUT_DIM];
__device__ float g_ssrc[N_NODES];
__device__ float g_sdst[N_NODES];

// ---------------------------------------------------------------------------
// Kernel A: Wh = h @ W ; s_src = Wh @ a[:128] ; s_dst = Wh @ a[128:]
// One block per row, 128 threads (one per output column).
// ---------------------------------------------------------------------------
__global__ void __launch_bounds__(128) wh_kernel(const float* __restrict__ h,
                                                 const float* __restrict__ W,
                                                 const float* __restrict__ a) {
    const int row = blockIdx.x;
    const int tid = threadIdx.x;

    __shared__ float hs[IN_DIM];
    __shared__ float red[8];

    hs[tid]       = h[row * IN_DIM + tid];
    hs[tid + 128] = h[row * IN_DIM + 128 + tid];
    __syncthreads();

    float acc = 0.f;
#pragma unroll 8
    for (int k = 0; k < IN_DIM; ++k)
        acc = fmaf(hs[k], W[k * OUT_DIM + tid], acc);

    g_Wh[row * OUT_DIM + tid] = acc;

    float v1 = acc * a[tid];
    float v2 = acc * a[OUT_DIM + tid];
#pragma unroll
    for (int o = 16; o > 0; o >>= 1) {
        v1 += __shfl_xor_sync(0xFFFFFFFFu, v1, o);
        v2 += __shfl_xor_sync(0xFFFFFFFFu, v2, o);
    }
    const int w = tid >> 5, l = tid & 31;
    if (l == 0) { red[w] = v1; red[4 + w] = v2; }
    __syncthreads();
    if (tid == 0) {
        g_ssrc[row] = red[0] + red[1] + red[2] + red[3];
        g_sdst[row] = red[4] + red[5] + red[6] + red[7];
    }
}

// ---------------------------------------------------------------------------
// Kernel B: out_i = (sum_j adj_ij * exp(leakyrelu(s_i + s_j)) * Wh_j) / rowsum
// Block: BI=16 rows. Loop j in tiles of BJ=64.
// 128 threads: thread t -> column group g = t&15 (8 cols), row pair
// (p, p+8) with p = t>>4. Each thread register-accumulates 2x8 outputs.
// ---------------------------------------------------------------------------
__global__ void __launch_bounds__(TPB) gat_kernel(const int* __restrict__ adj,
                                                  float* __restrict__ out) {
    __shared__ float whs[BJ * OUT_DIM];     // 32 KB: Wh tile, row-major [j][k]
    __shared__ float ws[BI * (BJ + 1)];     // weight tile, padded stride 65
    __shared__ float sis[BI];

    const int tid = threadIdx.x;
    const int i0  = blockIdx.x * BI;

    if (tid < BI) sis[tid] = g_ssrc[i0 + tid];

    const int g  = tid & 15;        // column group -> cols [g*8, g*8+8)
    const int p  = tid >> 4;        // 0..7
    const int rA = p;
    const int rB = p + 8;

    float4 a0lo = {0,0,0,0}, a0hi = {0,0,0,0};
    float4 a1lo = {0,0,0,0}, a1hi = {0,0,0,0};
    float rs0 = 0.f, rs1 = 0.f;

    for (int jt = 0; jt < N_NODES; jt += BJ) {
        __syncthreads();   // protects whs/ws reuse from previous iter; also sis on iter 0

        // --- load Wh tile [BJ][128] (2048 float4, 16 per thread, coalesced)
        const float4* src = (const float4*)(g_Wh + jt * OUT_DIM);
        float4* dst = (float4*)whs;
#pragma unroll
        for (int r = 0; r < 16; ++r)
            dst[tid + r * 128] = src[tid + r * 128];

        // --- compute weight tile (BI*BJ = 1024 entries, 8 per thread)
#pragma unroll
        for (int r = 0; r < 8; ++r) {
            const int idx = tid + r * 128;
            const int i = idx >> 6;      // /64
            const int j = idx & 63;
            const int aij = adj[(i0 + i) * N_NODES + jt + j];
            float e = sis[i] + g_sdst[jt + j];
            e = (e > 0.f) ? e : NEG_SLOPE * e;
            ws[i * (BJ + 1) + j] = aij ? __expf(e) : 0.f;
        }
        __syncthreads();

        // --- accumulate: 2 rows x 8 cols per thread
#pragma unroll 4
        for (int j = 0; j < BJ; ++j) {
            const float wA = ws[rA * (BJ + 1) + j];
            const float wB = ws[rB * (BJ + 1) + j];
            const float4 b0 = *(const float4*)&whs[j * OUT_DIM + g * 8];
            const float4 b1 = *(const float4*)&whs[j * OUT_DIM + g * 8 + 4];
            rs0 += wA; rs1 += wB;
            a0lo.x = fmaf(wA, b0.x, a0lo.x); a0lo.y = fmaf(wA, b0.y, a0lo.y);
            a0lo.z = fmaf(wA, b0.z, a0lo.z); a0lo.w = fmaf(wA, b0.w, a0lo.w);
            a0hi.x = fmaf(wA, b1.x, a0hi.x); a0hi.y = fmaf(wA, b1.y, a0hi.y);
            a0hi.z = fmaf(wA, b1.z, a0hi.z); a0hi.w = fmaf(wA, b1.w, a0hi.w);
            a1lo.x = fmaf(wB, b0.x, a1lo.x); a1lo.y = fmaf(wB, b0.y, a1lo.y);
            a1lo.z = fmaf(wB, b0.z, a1lo.z); a1lo.w = fmaf(wB, b0.w, a1lo.w);
            a1hi.x = fmaf(wB, b1.x, a1hi.x); a1hi.y = fmaf(wB, b1.y, a1hi.y);
            a1hi.z = fmaf(wB, b1.z, a1hi.z); a1hi.w = fmaf(wB, b1.w, a1hi.w);
        }
    }

    // --- normalize and write (rows with no neighbors -> 0, matches nan_to_num)
    const float inv0 = (rs0 > 0.f) ? (1.f / rs0) : 0.f;
    const float inv1 = (rs1 > 0.f) ? (1.f / rs1) : 0.f;

    float4 o;
    float* outA = out + (i0 + rA) * OUT_DIM + g * 8;
    float* outB = out + (i0 + rB) * OUT_DIM + g * 8;

    o.x = a0lo.x * inv0; o.y = a0lo.y * inv0; o.z = a0lo.z * inv0; o.w = a0lo.w * inv0;
    *(float4*)(outA)     = o;
    o.x = a0hi.x * inv0; o.y = a0hi.y * inv0; o.z = a0hi.z * inv0; o.w = a0hi.w * inv0;
    *(float4*)(outA + 4) = o;
    o.x = a1lo.x * inv1; o.y = a1lo.y * inv1; o.z = a1lo.z * inv1; o.w = a1lo.w * inv1;
    *(float4*)(outB)     = o;
    o.x = a1hi.x * inv1; o.y = a1hi.y * inv1; o.z = a1hi.z * inv1; o.w = a1hi.w * inv1;
    *(float4*)(outB + 4) = o;
}

// ---------------------------------------------------------------------------
extern "C" void kernel_launch(void* const* d_in, const int* in_sizes, int n_in,
                              void* d_out, int out_size) {
    const float* h   = (const float*)d_in[0];   // [8192,256] f32
    const int*   adj = (const int*)  d_in[1];   // [8192,8192] i32
    const float* W   = (const float*)d_in[2];   // [256,128] f32
    const float* a   = (const float*)d_in[3];   // [256] f32
    float* out = (float*)d_out;                 // [8192,128] f32

    wh_kernel<<<N_NODES, 128>>>(h, W, a);
    gat_kernel<<<N_NODES / BI, TPB>>>(adj, out);
}

// round 6
// speedup vs baseline: 4.2064x; 4.2064x over previous
#include <cuda_runtime.h>
#include <cuda_fp16.h>
#include <cstdint>

#define N_NODES 8192
#define IN_DIM  256
#define OUT_DIM 128
#define NEG_SLOPE 0.2f

// ---------------- scratch (no allocations allowed) ----------------
__device__ float  g_ssrc[N_NODES];
__device__ float  g_sdst[N_NODES];
__device__ __half g_Whrm[N_NODES * OUT_DIM];   // Wh row-major fp16 [node][feat]

__device__ __forceinline__ uint32_t smem_u32(const void* p) {
    uint32_t a;
    asm("{ .reg .u64 t; cvta.to.shared.u64 t, %1; cvt.u32.u64 %0, t; }" : "=r"(a) : "l"(p));
    return a;
}

__device__ __forceinline__ void ldsm_x4(uint32_t& r0, uint32_t& r1, uint32_t& r2, uint32_t& r3,
                                        uint32_t addr) {
    asm volatile("ldmatrix.sync.aligned.m8n8.x4.shared.b16 {%0,%1,%2,%3}, [%4];"
                 : "=r"(r0), "=r"(r1), "=r"(r2), "=r"(r3) : "r"(addr));
}
__device__ __forceinline__ void ldsm_x4_t(uint32_t& r0, uint32_t& r1, uint32_t& r2, uint32_t& r3,
                                          uint32_t addr) {
    asm volatile("ldmatrix.sync.aligned.m8n8.x4.trans.shared.b16 {%0,%1,%2,%3}, [%4];"
                 : "=r"(r0), "=r"(r1), "=r"(r2), "=r"(r3) : "r"(addr));
}
__device__ __forceinline__ void mma_16816(float& c0, float& c1, float& c2, float& c3,
                                          uint32_t a0, uint32_t a1, uint32_t a2, uint32_t a3,
                                          uint32_t b0, uint32_t b1) {
    asm volatile("mma.sync.aligned.m16n8k16.row.col.f32.f16.f16.f32 "
                 "{%0,%1,%2,%3}, {%4,%5,%6,%7}, {%8,%9}, {%0,%1,%2,%3};"
                 : "+f"(c0), "+f"(c1), "+f"(c2), "+f"(c3)
                 : "r"(a0), "r"(a1), "r"(a2), "r"(a3), "r"(b0), "r"(b1));
}

// ---------------------------------------------------------------------------
// Kernel A: Wh = h @ W (fp32 acc -> fp16), s_src = Wh@a[:128], s_dst = Wh@a[128:]
// ---------------------------------------------------------------------------
__global__ void __launch_bounds__(128) wh_kernel(const float* __restrict__ h,
                                                 const float* __restrict__ W,
                                                 const float* __restrict__ a) {
    const int row = blockIdx.x;
    const int tid = threadIdx.x;

    __shared__ float hs[IN_DIM];
    __shared__ float red[8];

    hs[tid]       = h[row * IN_DIM + tid];
    hs[tid + 128] = h[row * IN_DIM + 128 + tid];
    __syncthreads();

    float acc = 0.f;
#pragma unroll 8
    for (int k = 0; k < IN_DIM; ++k)
        acc = fmaf(hs[k], W[k * OUT_DIM + tid], acc);

    g_Whrm[row * OUT_DIM + tid] = __float2half(acc);

    float v1 = acc * a[tid];
    float v2 = acc * a[OUT_DIM + tid];
#pragma unroll
    for (int o = 16; o > 0; o >>= 1) {
        v1 += __shfl_xor_sync(0xFFFFFFFFu, v1, o);
        v2 += __shfl_xor_sync(0xFFFFFFFFu, v2, o);
    }
    const int w = tid >> 5, l = tid & 31;
    if (l == 0) { red[w] = v1; red[4 + w] = v2; }
    __syncthreads();
    if (tid == 0) {
        g_ssrc[row] = red[0] + red[1] + red[2] + red[3];
        g_sdst[row] = red[4] + red[5] + red[6] + red[7];
    }
}

// ---------------------------------------------------------------------------
// Kernel B: flash-GAT with warp MMA (m16n8k16 fp16 HMMA).
// CTA = 64 output rows x 128 cols. 8 warps in 2(m) x 4(n) grid, 32x32 each.
// j-tiles of 64; adj prefetched one tile ahead; XOR-swizzled smem.
// ---------------------------------------------------------------------------
#define RT 64     // rows per CTA
#define KT 64     // j (K) per tile
#define NT (N_NODES / KT)

__global__ void __launch_bounds__(256) gat_kernel(const int* __restrict__ adj,
                                                  float* __restrict__ out) {
    __shared__ alignas(16) char Bs[KT * 256];   // [k][feat] fp16, 256B rows, swizzled
    __shared__ alignas(16) char As[RT * 128];   // [m][k]    fp16, 128B rows, swizzled
    __shared__ float srow[RT];

    const int tid  = threadIdx.x;
    const int lane = tid & 31;
    const int wid  = tid >> 5;
    const int i0   = blockIdx.x * RT;
    const int wm   = wid & 1;       // 0..1 -> rows wm*32
    const int wn   = wid >> 1;      // 0..3 -> cols wn*32

    // P-production mapping: thread -> row (tid>>2), 16 j's (q*16..q*16+15)
    const int prow = tid >> 2;
    const int q    = tid & 3;
    const float si = g_ssrc[i0 + prow];
    float rsum = 0.f;

    float acc[2][4][4];
#pragma unroll
    for (int i = 0; i < 2; ++i)
#pragma unroll
        for (int j = 0; j < 4; ++j)
#pragma unroll
            for (int k = 0; k < 4; ++k) acc[i][j][k] = 0.f;

    const uint32_t sbA = smem_u32(As);
    const uint32_t sbB = smem_u32(Bs);

    // ldmatrix lane addressing (constant parts)
    const int l15 = lane & 15;
    const int lhi = lane >> 4;                  // 0/1
    const uint32_t aswz = (uint32_t)((l15 & 7) << 4);
    // A: addr = sbA + (wm*32 + mf*16 + l15)*128 + ((kf*32 + lhi*16) ^ aswz)
    const uint32_t abase = sbA + (uint32_t)(wm * 32 + l15) * 128;
    // B: addr = sbB + (kf*16 + l15)*256 + ((wn*64 + bf*32 + lhi*16) ^ ((l15&7)<<4))
    const uint32_t bbase = sbB + (uint32_t)l15 * 256;

    const int* aptr = adj + (size_t)(i0 + prow) * N_NODES + q * 16;
    int4 pref[4];
#pragma unroll
    for (int v = 0; v < 4; ++v) pref[v] = *(const int4*)(aptr + v * 4);

    for (int t = 0; t < NT; ++t) {
        const int j0 = t * KT;

        // ---- B tile: Wh rows j0..j0+63, 128 feats (16 KB), swizzled
#pragma unroll
        for (int p = 0; p < 4; ++p) {
            const int idx = tid + p * 256;
            const int br = idx >> 4;
            const int bg = idx & 15;
            const uint4 val = *(const uint4*)(g_Whrm + (size_t)(j0 + br) * OUT_DIM + bg * 8);
            *(uint4*)(Bs + br * 256 + ((bg * 16) ^ ((br & 7) << 4))) = val;
        }

        // ---- A tile: P = adj ? exp(leakyrelu(si+sj)) : 0 (fp16, swizzled)
#pragma unroll
        for (int v = 0; v < 4; ++v) {
            const float4 sj = *(const float4*)(g_sdst + j0 + q * 16 + v * 4);
            const int4 av = pref[v];
            float e0 = si + sj.x; e0 = fmaxf(e0, NEG_SLOPE * e0);
            float e1 = si + sj.y; e1 = fmaxf(e1, NEG_SLOPE * e1);
            float e2 = si + sj.z; e2 = fmaxf(e2, NEG_SLOPE * e2);
            float e3 = si + sj.w; e3 = fmaxf(e3, NEG_SLOPE * e3);
            const float p0 = av.x ? __expf(e0) : 0.f;
            const float p1 = av.y ? __expf(e1) : 0.f;
            const float p2 = av.z ? __expf(e2) : 0.f;
            const float p3 = av.w ? __expf(e3) : 0.f;
            rsum += (p0 + p1) + (p2 + p3);
            const __half2 h01 = __floats2half2_rn(p0, p1);
            const __half2 h23 = __floats2half2_rn(p2, p3);
            uint2 pk;
            pk.x = *(const uint32_t*)&h01;
            pk.y = *(const uint32_t*)&h23;
            *(uint2*)(As + prow * 128 + ((q * 32 + v * 8) ^ ((prow & 7) << 4))) = pk;
        }
        __syncthreads();

        // ---- prefetch adj for next tile (overlaps MMA below)
        if (t + 1 < NT) {
            const int* np = aptr + (j0 + KT);
#pragma unroll
            for (int v = 0; v < 4; ++v) pref[v] = *(const int4*)(np + v * 4);
        }

        // ---- MMA phase: 4 k-fragments of 16
#pragma unroll
        for (int kf = 0; kf < 4; ++kf) {
            uint32_t a[2][4];
#pragma unroll
            for (int mf = 0; mf < 2; ++mf)
                ldsm_x4(a[mf][0], a[mf][1], a[mf][2], a[mf][3],
                        abase + (uint32_t)(mf * 16) * 128 +
                        (((uint32_t)(kf * 32 + lhi * 16)) ^ aswz));
            uint32_t b[4][2];
#pragma unroll
            for (int bf = 0; bf < 2; ++bf)
                ldsm_x4_t(b[bf * 2][0], b[bf * 2][1], b[bf * 2 + 1][0], b[bf * 2 + 1][1],
                          bbase + (uint32_t)(kf * 16) * 256 +
                          (((uint32_t)(wn * 64 + bf * 32 + lhi * 16)) ^ aswz));
#pragma unroll
            for (int mf = 0; mf < 2; ++mf)
#pragma unroll
                for (int nf = 0; nf < 4; ++nf)
                    mma_16816(acc[mf][nf][0], acc[mf][nf][1], acc[mf][nf][2], acc[mf][nf][3],
                              a[mf][0], a[mf][1], a[mf][2], a[mf][3],
                              b[nf][0], b[nf][1]);
        }
        __syncthreads();
    }

    // ---- row sums: 4 threads per row -> shuffle reduce, store to smem
    rsum += __shfl_xor_sync(0xFFFFFFFFu, rsum, 1);
    rsum += __shfl_xor_sync(0xFFFFFFFFu, rsum, 2);
    if (q == 0) srow[prow] = rsum;
    __syncthreads();

    // ---- epilogue: scale by 1/rowsum, write out
#pragma unroll
    for (int mf = 0; mf < 2; ++mf) {
        const int rlo = wm * 32 + mf * 16 + (lane >> 2);
        const int rhi = rlo + 8;
        const float slo = srow[rlo];
        const float shi = srow[rhi];
        const float invlo = (slo > 0.f) ? (1.f / slo) : 0.f;
        const float invhi = (shi > 0.f) ? (1.f / shi) : 0.f;
        float* outlo = out + (size_t)(i0 + rlo) * OUT_DIM + wn * 32 + (lane & 3) * 2;
        float* outhi = out + (size_t)(i0 + rhi) * OUT_DIM + wn * 32 + (lane & 3) * 2;
#pragma unroll
        for (int nf = 0; nf < 4; ++nf) {
            float2 v;
            v.x = acc[mf][nf][0] * invlo; v.y = acc[mf][nf][1] * invlo;
            *(float2*)(outlo + nf * 8) = v;
            v.x = acc[mf][nf][2] * invhi; v.y = acc[mf][nf][3] * invhi;
            *(float2*)(outhi + nf * 8) = v;
        }
    }
}

// ---------------------------------------------------------------------------
extern "C" void kernel_launch(void* const* d_in, const int* in_sizes, int n_in,
                              void* d_out, int out_size) {
    const float* h   = (const float*)d_in[0];   // [8192,256] f32
    const int*   adj = (const int*)  d_in[1];   // [8192,8192] i32
    const float* W   = (const float*)d_in[2];   // [256,128] f32
    const float* a   = (const float*)d_in[3];   // [256] f32
    float* out = (float*)d_out;                 // [8192,128] f32

    wh_kernel<<<N_NODES, 128>>>(h, W, a);
    gat_kernel<<<N_NODES / RT, 256>>>(adj, out);
}

// round 7
// speedup vs baseline: 6.4879x; 1.5424x over previous
#include <cuda_runtime.h>
#include <cuda_fp16.h>
#include <cstdint>

#define N_NODES 8192
#define IN_DIM  256
#define OUT_DIM 128
#define NEG_SLOPE 0.2f
#define LOG2E 1.4426950408889634f

// ---------------- scratch (no allocations allowed) ----------------
__device__ float  g_ssrc[N_NODES];             // s_src * log2(e)
__device__ float  g_sdst[N_NODES];             // s_dst * log2(e)
__device__ __half g_Whrm[N_NODES * OUT_DIM];   // Wh row-major fp16 [node][feat]

__device__ __forceinline__ uint32_t smem_u32(const void* p) {
    uint32_t a;
    asm("{ .reg .u64 t; cvta.to.shared.u64 t, %1; cvt.u32.u64 %0, t; }" : "=r"(a) : "l"(p));
    return a;
}
__device__ __forceinline__ void cp16(uint32_t dst, const void* src) {
    asm volatile("cp.async.cg.shared.global [%0], [%1], 16;" :: "r"(dst), "l"(src) : "memory");
}
#define CP_COMMIT() asm volatile("cp.async.commit_group;" ::: "memory")
#define CP_WAIT2()  asm volatile("cp.async.wait_group 2;" ::: "memory")

__device__ __forceinline__ float ex2f(float x) {
    float y; asm("ex2.approx.f32 %0, %1;" : "=f"(y) : "f"(x)); return y;
}

__device__ __forceinline__ void ldsm_x4(uint32_t& r0, uint32_t& r1, uint32_t& r2, uint32_t& r3,
                                        uint32_t addr) {
    asm volatile("ldmatrix.sync.aligned.m8n8.x4.shared.b16 {%0,%1,%2,%3}, [%4];"
                 : "=r"(r0), "=r"(r1), "=r"(r2), "=r"(r3) : "r"(addr));
}
__device__ __forceinline__ void ldsm_x4_t(uint32_t& r0, uint32_t& r1, uint32_t& r2, uint32_t& r3,
                                          uint32_t addr) {
    asm volatile("ldmatrix.sync.aligned.m8n8.x4.trans.shared.b16 {%0,%1,%2,%3}, [%4];"
                 : "=r"(r0), "=r"(r1), "=r"(r2), "=r"(r3) : "r"(addr));
}
__device__ __forceinline__ void mma_16816(float& c0, float& c1, float& c2, float& c3,
                                          uint32_t a0, uint32_t a1, uint32_t a2, uint32_t a3,
                                          uint32_t b0, uint32_t b1) {
    asm volatile("mma.sync.aligned.m16n8k16.row.col.f32.f16.f16.f32 "
                 "{%0,%1,%2,%3}, {%4,%5,%6,%7}, {%8,%9}, {%0,%1,%2,%3};"
                 : "+f"(c0), "+f"(c1), "+f"(c2), "+f"(c3)
                 : "r"(a0), "r"(a1), "r"(a2), "r"(a3), "r"(b0), "r"(b1));
}

// ---------------------------------------------------------------------------
// Kernel A: Wh = h @ W (fp32 acc -> fp16); scores stored pre-scaled by log2(e)
// ---------------------------------------------------------------------------
__global__ void __launch_bounds__(128) wh_kernel(const float* __restrict__ h,
                                                 const float* __restrict__ W,
                                                 const float* __restrict__ a) {
    const int row = blockIdx.x;
    const int tid = threadIdx.x;

    __shared__ float hs[IN_DIM];
    __shared__ float red[8];

    hs[tid]       = h[row * IN_DIM + tid];
    hs[tid + 128] = h[row * IN_DIM + 128 + tid];
    __syncthreads();

    float acc = 0.f;
#pragma unroll 8
    for (int k = 0; k < IN_DIM; ++k)
        acc = fmaf(hs[k], W[k * OUT_DIM + tid], acc);

    g_Whrm[row * OUT_DIM + tid] = __float2half(acc);

    float v1 = acc * a[tid];
    float v2 = acc * a[OUT_DIM + tid];
#pragma unroll
    for (int o = 16; o > 0; o >>= 1) {
        v1 += __shfl_xor_sync(0xFFFFFFFFu, v1, o);
        v2 += __shfl_xor_sync(0xFFFFFFFFu, v2, o);
    }
    const int w = tid >> 5, l = tid & 31;
    if (l == 0) { red[w] = v1; red[4 + w] = v2; }
    __syncthreads();
    if (tid == 0) {
        g_ssrc[row] = (red[0] + red[1] + red[2] + red[3]) * LOG2E;
        g_sdst[row] = (red[4] + red[5] + red[6] + red[7]) * LOG2E;
    }
}

// ---------------------------------------------------------------------------
// Kernel B: flash-GAT, HMMA + 3-stage cp.async pipeline for adj and Wh tiles.
// CTA = 64 rows x 128 cols, 8 warps 2(m) x 4(n). j-tiles of 64.
// ---------------------------------------------------------------------------
#define RT 64
#define KT 64
#define NT (N_NODES / KT)
#define DEPTH 3

// smem layout (bytes)
#define ADJ_ST(s) ((s) * 16384)            // 3 x 16KB adj stages  [row][64 ints]
#define BS_ST(s)  (49152 + (s) * 16384)    // 3 x 16KB Bs stages   [k][128 fp16] swizzled
#define AS_OFF    98304                    // 8KB  As [m][64 fp16] swizzled
#define SDST_OFF  106496                   // 32KB staged g_sdst (scaled)
#define SROW_OFF  139264                   // 256B row sums
#define SMEM_TOT  139520

__global__ void __launch_bounds__(256) gat_kernel(const int* __restrict__ adj,
                                                  float* __restrict__ out) {
    extern __shared__ char smem[];
    const uint32_t sb = smem_u32(smem);

    const int tid  = threadIdx.x;
    const int lane = tid & 31;
    const int wid  = tid >> 5;
    const int i0   = blockIdx.x * RT;
    const int wm   = wid & 1;
    const int wn   = wid >> 1;

    // P-production mapping: thread -> row prow, 16 j's starting q*16
    const int prow = tid >> 2;
    const int q    = tid & 3;
    const float si2 = g_ssrc[i0 + prow];    // already * log2(e)
    float rsum = 0.f;

    float acc[2][4][4];
#pragma unroll
    for (int i = 0; i < 2; ++i)
#pragma unroll
        for (int j = 0; j < 4; ++j)
#pragma unroll
            for (int k = 0; k < 4; ++k) acc[i][j][k] = 0.f;

    // ldmatrix lane addressing
    const int l15 = lane & 15;
    const int lhi = lane >> 4;
    const uint32_t aswz  = (uint32_t)((l15 & 7) << 4);
    const uint32_t abase = sb + AS_OFF + (uint32_t)(wm * 32 + l15) * 128;

    const int* aptr = adj + (size_t)(i0 + prow) * N_NODES + q * 16;
    const uint32_t adj_thr_off = (uint32_t)(prow * 256 + q * 64);

    // ---- stage g_sdst into smem (visible after first loop-top barrier)
    {
        float4* dst = (float4*)(smem + SDST_OFF);
        const float4* src = (const float4*)g_sdst;
#pragma unroll
        for (int r = 0; r < 8; ++r) dst[tid + r * 256] = src[tid + r * 256];
    }

    // ---- stage issue helper
    auto issue = [&](int tt) {
        const int slot = tt % DEPTH;
        const uint32_t ab = sb + ADJ_ST(slot) + adj_thr_off;
        const char* asrc = (const char*)aptr + (size_t)tt * KT * 4;
#pragma unroll
        for (int v = 0; v < 4; ++v) cp16(ab + v * 16, asrc + v * 16);
        const uint32_t bb = sb + BS_ST(slot);
#pragma unroll
        for (int p = 0; p < 4; ++p) {
            const int idx = tid + p * 256;
            const int br = idx >> 4;
            const int bg = idx & 15;
            cp16(bb + br * 256 + ((bg * 16) ^ ((br & 7) << 4)),
                 g_Whrm + (size_t)(tt * KT + br) * OUT_DIM + bg * 8);
        }
    };

    // ---- prologue: 3 stages in flight
#pragma unroll
    for (int s = 0; s < DEPTH; ++s) { issue(s); CP_COMMIT(); }

    for (int t = 0; t < NT; ++t) {
        const int slot = t % DEPTH;

        CP_WAIT2();
        __syncthreads();                         // S1: stage t visible everywhere; As free

        // ---- P phase: adj from smem stage -> masked exp2 -> As (fp16, swizzled)
        const char* adjS = smem + ADJ_ST(slot) + adj_thr_off;
        const float* sdS = (const float*)(smem + SDST_OFF) + t * KT + q * 16;
#pragma unroll
        for (int v = 0; v < 4; ++v) {
            const int4 av   = *(const int4*)(adjS + v * 16);
            const float4 sj = *(const float4*)(sdS + v * 4);
            float e0 = si2 + sj.x; e0 = fmaxf(e0, NEG_SLOPE * e0);
            float e1 = si2 + sj.y; e1 = fmaxf(e1, NEG_SLOPE * e1);
            float e2 = si2 + sj.z; e2 = fmaxf(e2, NEG_SLOPE * e2);
            float e3 = si2 + sj.w; e3 = fmaxf(e3, NEG_SLOPE * e3);
            float p0 = ex2f(e0); p0 = av.x ? p0 : 0.f;
            float p1 = ex2f(e1); p1 = av.y ? p1 : 0.f;
            float p2 = ex2f(e2); p2 = av.z ? p2 : 0.f;
            float p3 = ex2f(e3); p3 = av.w ? p3 : 0.f;
            rsum += (p0 + p1) + (p2 + p3);
            const __half2 h01 = __floats2half2_rn(p0, p1);
            const __half2 h23 = __floats2half2_rn(p2, p3);
            uint2 pk;
            pk.x = *(const uint32_t*)&h01;
            pk.y = *(const uint32_t*)&h23;
            *(uint2*)(smem + AS_OFF + prow * 128 + ((q * 32 + v * 8) ^ ((prow & 7) << 4))) = pk;
        }
        __syncthreads();                         // S2: As complete

        // ---- MMA phase
        const uint32_t bbase = sb + BS_ST(slot) + (uint32_t)l15 * 256;
#pragma unroll
        for (int kf = 0; kf < 4; ++kf) {
            uint32_t a[2][4];
#pragma unroll
            for (int mf = 0; mf < 2; ++mf)
                ldsm_x4(a[mf][0], a[mf][1], a[mf][2], a[mf][3],
                        abase + (uint32_t)(mf * 16) * 128 +
                        (((uint32_t)(kf * 32 + lhi * 16)) ^ aswz));
            uint32_t b[4][2];
#pragma unroll
            for (int bf = 0; bf < 2; ++bf)
                ldsm_x4_t(b[bf * 2][0], b[bf * 2][1], b[bf * 2 + 1][0], b[bf * 2 + 1][1],
                          bbase + (uint32_t)(kf * 16) * 256 +
                          (((uint32_t)(wn * 64 + bf * 32 + lhi * 16)) ^ aswz));
#pragma unroll
            for (int mf = 0; mf < 2; ++mf)
#pragma unroll
                for (int nf = 0; nf < 4; ++nf)
                    mma_16816(acc[mf][nf][0], acc[mf][nf][1], acc[mf][nf][2], acc[mf][nf][3],
                              a[mf][0], a[mf][1], a[mf][2], a[mf][3],
                              b[nf][0], b[nf][1]);
        }
        __syncthreads();                         // S3: slot consumed, safe to refill

        if (t + DEPTH < NT) issue(t + DEPTH);
        CP_COMMIT();                             // commit every iter (possibly empty)
    }

    // ---- row sums: 4 threads/row shuffle reduce
    rsum += __shfl_xor_sync(0xFFFFFFFFu, rsum, 1);
    rsum += __shfl_xor_sync(0xFFFFFFFFu, rsum, 2);
    float* srow = (float*)(smem + SROW_OFF);
    if (q == 0) srow[prow] = rsum;
    __syncthreads();

    // ---- epilogue
#pragma unroll
    for (int mf = 0; mf < 2; ++mf) {
        const int rlo = wm * 32 + mf * 16 + (lane >> 2);
        const int rhi = rlo + 8;
        const float slo = srow[rlo];
        const float shi = srow[rhi];
        const float invlo = (slo > 0.f) ? (1.f / slo) : 0.f;
        const float invhi = (shi > 0.f) ? (1.f / shi) : 0.f;
        float* outlo = out + (size_t)(i0 + rlo) * OUT_DIM + wn * 32 + (lane & 3) * 2;
        float* outhi = out + (size_t)(i0 + rhi) * OUT_DIM + wn * 32 + (lane & 3) * 2;
#pragma unroll
        for (int nf = 0; nf < 4; ++nf) {
            float2 v;
            v.x = acc[mf][nf][0] * invlo; v.y = acc[mf][nf][1] * invlo;
            *(float2*)(outlo + nf * 8) = v;
            v.x = acc[mf][nf][2] * invhi; v.y = acc[mf][nf][3] * invhi;
            *(float2*)(outhi + nf * 8) = v;
        }
    }
}

// ---------------------------------------------------------------------------
extern "C" void kernel_launch(void* const* d_in, const int* in_sizes, int n_in,
                              void* d_out, int out_size) {
    const float* h   = (const float*)d_in[0];   // [8192,256] f32
    const int*   adj = (const int*)  d_in[1];   // [8192,8192] i32
    const float* W   = (const float*)d_in[2];   // [256,128] f32
    const float* a   = (const float*)d_in[3];   // [256] f32
    float* out = (float*)d_out;                 // [8192,128] f32

    cudaFuncSetAttribute(gat_kernel, cudaFuncAttributeMaxDynamicSharedMemorySize, SMEM_TOT);

    wh_kernel<<<N_NODES, 128>>>(h, W, a);
    gat_kernel<<<N_NODES / RT, 256, SMEM_TOT>>>(adj, out);
}

// round 8
// speedup vs baseline: 8.2222x; 1.2673x over previous
#include <cuda_runtime.h>
#include <cuda_fp16.h>
#include <cstdint>

#define N_NODES 8192
#define IN_DIM  256
#define OUT_DIM 128
#define NEG_SLOPE 0.2f
#define LOG2E 1.4426950408889634f

// ---------------- scratch (no allocations allowed) ----------------
__device__ float  g_ssrc[N_NODES];             // s_src * log2(e)
__device__ float  g_sdst[N_NODES];             // s_dst * log2(e)
__device__ __half g_Whrm[N_NODES * OUT_DIM];   // Wh row-major fp16 [node][feat]

__device__ __forceinline__ uint32_t smem_u32(const void* p) {
    uint32_t a;
    asm("{ .reg .u64 t; cvta.to.shared.u64 t, %1; cvt.u32.u64 %0, t; }" : "=r"(a) : "l"(p));
    return a;
}
__device__ __forceinline__ void cp16(uint32_t dst, const void* src) {
    asm volatile("cp.async.cg.shared.global [%0], [%1], 16;" :: "r"(dst), "l"(src) : "memory");
}
#define CP_COMMIT() asm volatile("cp.async.commit_group;" ::: "memory")
#define CP_WAIT2()  asm volatile("cp.async.wait_group 2;" ::: "memory")

__device__ __forceinline__ float ex2f(float x) {
    float y; asm("ex2.approx.f32 %0, %1;" : "=f"(y) : "f"(x)); return y;
}

__device__ __forceinline__ void ldsm_x4(uint32_t& r0, uint32_t& r1, uint32_t& r2, uint32_t& r3,
                                        uint32_t addr) {
    asm volatile("ldmatrix.sync.aligned.m8n8.x4.shared.b16 {%0,%1,%2,%3}, [%4];"
                 : "=r"(r0), "=r"(r1), "=r"(r2), "=r"(r3) : "r"(addr));
}
__device__ __forceinline__ void ldsm_x4_t(uint32_t& r0, uint32_t& r1, uint32_t& r2, uint32_t& r3,
                                          uint32_t addr) {
    asm volatile("ldmatrix.sync.aligned.m8n8.x4.trans.shared.b16 {%0,%1,%2,%3}, [%4];"
                 : "=r"(r0), "=r"(r1), "=r"(r2), "=r"(r3) : "r"(addr));
}
__device__ __forceinline__ void mma_16816(float& c0, float& c1, float& c2, float& c3,
                                          uint32_t a0, uint32_t a1, uint32_t a2, uint32_t a3,
                                          uint32_t b0, uint32_t b1) {
    asm volatile("mma.sync.aligned.m16n8k16.row.col.f32.f16.f16.f32 "
                 "{%0,%1,%2,%3}, {%4,%5,%6,%7}, {%8,%9}, {%0,%1,%2,%3};"
                 : "+f"(c0), "+f"(c1), "+f"(c2), "+f"(c3)
                 : "r"(a0), "r"(a1), "r"(a2), "r"(a3), "r"(b0), "r"(b1));
}

// ---------------------------------------------------------------------------
// Kernel A: tiled fp32 GEMM. Block = 64 rows, 256 threads.
// Thread (ry,tx): rows ry*8..+8, cols tx*4..+4 (acc 8x4).
// Scores fused: per-row dot with a_src/a_dst via warp shfl reduce.
// ---------------------------------------------------------------------------
__global__ void __launch_bounds__(256) wh_kernel(const float* __restrict__ h,
                                                 const float* __restrict__ W,
                                                 const float* __restrict__ a) {
    __shared__ float hs[64 * 32];      // h chunk  [row][k]
    __shared__ float ws[32 * 128];     // W chunk  [k][col]

    const int r0  = blockIdx.x * 64;
    const int tid = threadIdx.x;
    const int tx  = tid & 31;          // col group: cols tx*4
    const int ry  = tid >> 5;          // warp id: rows ry*8..+8

    float acc[8][4];
#pragma unroll
    for (int i = 0; i < 8; ++i)
#pragma unroll
        for (int c = 0; c < 4; ++c) acc[i][c] = 0.f;

    for (int ck = 0; ck < 8; ++ck) {
        __syncthreads();
        // h chunk: 64x32 = 512 float4
#pragma unroll
        for (int p = 0; p < 2; ++p) {
            const int idx = tid + p * 256;
            const int row = idx >> 3, kq = idx & 7;
            ((float4*)hs)[row * 8 + kq] =
                *(const float4*)(h + (size_t)(r0 + row) * IN_DIM + ck * 32 + kq * 4);
        }
        // W chunk: 32x128 = 1024 float4
#pragma unroll
        for (int p = 0; p < 4; ++p) {
            const int idx = tid + p * 256;
            const int kr = idx >> 5, cq = idx & 31;
            ((float4*)ws)[kr * 32 + cq] =
                *(const float4*)(W + (size_t)(ck * 32 + kr) * OUT_DIM + cq * 4);
        }
        __syncthreads();
#pragma unroll 4
        for (int kk = 0; kk < 32; ++kk) {
            const float4 wv = ((const float4*)ws)[kk * 32 + tx];
#pragma unroll
            for (int i = 0; i < 8; ++i) {
                const float hv = hs[(ry * 8 + i) * 32 + kk];   // warp broadcast
                acc[i][0] = fmaf(hv, wv.x, acc[i][0]);
                acc[i][1] = fmaf(hv, wv.y, acc[i][1]);
                acc[i][2] = fmaf(hv, wv.z, acc[i][2]);
                acc[i][3] = fmaf(hv, wv.w, acc[i][3]);
            }
        }
    }

    // store Wh (fp16)
#pragma unroll
    for (int i = 0; i < 8; ++i) {
        const int row = r0 + ry * 8 + i;
        const __half2 lo = __floats2half2_rn(acc[i][0], acc[i][1]);
        const __half2 hi = __floats2half2_rn(acc[i][2], acc[i][3]);
        uint2 v;
        v.x = *(const uint32_t*)&lo;
        v.y = *(const uint32_t*)&hi;
        *(uint2*)(g_Whrm + (size_t)row * OUT_DIM + tx * 4) = v;
    }

    // fused scores (same-row threads = one warp)
    const float4 as4 = *(const float4*)(a + tx * 4);
    const float4 ad4 = *(const float4*)(a + OUT_DIM + tx * 4);
#pragma unroll
    for (int i = 0; i < 8; ++i) {
        float v1 = acc[i][0] * as4.x + acc[i][1] * as4.y + acc[i][2] * as4.z + acc[i][3] * as4.w;
        float v2 = acc[i][0] * ad4.x + acc[i][1] * ad4.y + acc[i][2] * ad4.z + acc[i][3] * ad4.w;
#pragma unroll
        for (int o = 16; o > 0; o >>= 1) {
            v1 += __shfl_xor_sync(0xFFFFFFFFu, v1, o);
            v2 += __shfl_xor_sync(0xFFFFFFFFu, v2, o);
        }
        if (tx == 0) {
            g_ssrc[r0 + ry * 8 + i] = v1 * LOG2E;
            g_sdst[r0 + ry * 8 + i] = v2 * LOG2E;
        }
    }
}

// ---------------------------------------------------------------------------
// Kernel B: flash-GAT, HMMA + 3-stage cp.async pipeline. 512 threads (16 warps).
// CTA = 64 rows x 128 cols; warp grid 4(m) x 4(n), each 16x32.
// ---------------------------------------------------------------------------
#define RT 64
#define KT 64
#define NT (N_NODES / KT)
#define DEPTH 3

#define ADJ_ST(s) ((s) * 16384)            // 3 x 16KB adj stages  [row][64 ints]
#define BS_ST(s)  (49152 + (s) * 16384)    // 3 x 16KB Bs stages   [k][128 fp16] swizzled
#define AS_OFF    98304                    // 8KB  As [m][64 fp16] swizzled
#define SDST_OFF  106496                   // 32KB staged g_sdst (scaled)
#define SROW_OFF  139264                   // 256B row sums
#define SMEM_TOT  139520

__global__ void __launch_bounds__(512) gat_kernel(const int* __restrict__ adj,
                                                  float* __restrict__ out) {
    extern __shared__ char smem[];
    const uint32_t sb = smem_u32(smem);

    const int tid  = threadIdx.x;
    const int lane = tid & 31;
    const int wid  = tid >> 5;
    const int i0   = blockIdx.x * RT;
    const int wm   = wid & 3;       // rows wm*16
    const int wn   = wid >> 2;      // cols wn*32

    // P-production mapping: thread -> row prow, 8 j's starting q*8
    const int prow = tid >> 3;
    const int q    = tid & 7;
    const float si2 = g_ssrc[i0 + prow];
    float rsum = 0.f;

    float acc[4][4];
#pragma unroll
    for (int j = 0; j < 4; ++j)
#pragma unroll
        for (int k = 0; k < 4; ++k) acc[j][k] = 0.f;

    const int l15 = lane & 15;
    const int lhi = lane >> 4;
    const uint32_t aswz  = (uint32_t)((l15 & 7) << 4);
    const uint32_t abase = sb + AS_OFF + (uint32_t)(wm * 16 + l15) * 128;

    const int* aptr = adj + (size_t)(i0 + prow) * N_NODES + q * 8;
    const uint32_t adj_thr_off = (uint32_t)(prow * 256 + q * 32);

    // ---- stage g_sdst (8192 floats = 2048 float4)
    {
        float4* dst = (float4*)(smem + SDST_OFF);
        const float4* src = (const float4*)g_sdst;
#pragma unroll
        for (int r = 0; r < 4; ++r) dst[tid + r * 512] = src[tid + r * 512];
    }

    auto issue = [&](int tt) {
        const int slot = tt % DEPTH;
        const uint32_t ab = sb + ADJ_ST(slot) + adj_thr_off;
        const char* asrc = (const char*)aptr + (size_t)tt * KT * 4;
#pragma unroll
        for (int v = 0; v < 2; ++v) cp16(ab + v * 16, asrc + v * 16);
        const uint32_t bb = sb + BS_ST(slot);
#pragma unroll
        for (int p = 0; p < 2; ++p) {
            const int idx = tid + p * 512;
            const int br = idx >> 4;
            const int bg = idx & 15;
            cp16(bb + br * 256 + ((bg * 16) ^ ((br & 7) << 4)),
                 g_Whrm + (size_t)(tt * KT + br) * OUT_DIM + bg * 8);
        }
    };

#pragma unroll
    for (int s = 0; s < DEPTH; ++s) { issue(s); CP_COMMIT(); }

    for (int t = 0; t < NT; ++t) {
        const int slot = t % DEPTH;

        CP_WAIT2();
        __syncthreads();                         // stage t visible; As free

        // ---- P phase: 8 elements per thread
        const char* adjS = smem + ADJ_ST(slot) + adj_thr_off;
        const float* sdS = (const float*)(smem + SDST_OFF) + t * KT + q * 8;
#pragma unroll
        for (int v = 0; v < 2; ++v) {
            const int4 av   = *(const int4*)(adjS + v * 16);
            const float4 sj = *(const float4*)(sdS + v * 4);
            float e0 = si2 + sj.x; e0 = fmaxf(e0, NEG_SLOPE * e0);
            float e1 = si2 + sj.y; e1 = fmaxf(e1, NEG_SLOPE * e1);
            float e2 = si2 + sj.z; e2 = fmaxf(e2, NEG_SLOPE * e2);
            float e3 = si2 + sj.w; e3 = fmaxf(e3, NEG_SLOPE * e3);
            float p0 = ex2f(e0); p0 = av.x ? p0 : 0.f;
            float p1 = ex2f(e1); p1 = av.y ? p1 : 0.f;
            float p2 = ex2f(e2); p2 = av.z ? p2 : 0.f;
            float p3 = ex2f(e3); p3 = av.w ? p3 : 0.f;
            rsum += (p0 + p1) + (p2 + p3);
            const __half2 h01 = __floats2half2_rn(p0, p1);
            const __half2 h23 = __floats2half2_rn(p2, p3);
            uint2 pk;
            pk.x = *(const uint32_t*)&h01;
            pk.y = *(const uint32_t*)&h23;
            *(uint2*)(smem + AS_OFF + prow * 128 + ((q * 16 + v * 8) ^ ((prow & 7) << 4))) = pk;
        }
        __syncthreads();                         // As complete

        // ---- MMA phase (per warp: m16 x n32)
        const uint32_t bbase = sb + BS_ST(slot) + (uint32_t)l15 * 256;
#pragma unroll
        for (int kf = 0; kf < 4; ++kf) {
            uint32_t a[4];
            ldsm_x4(a[0], a[1], a[2], a[3],
                    abase + (((uint32_t)(kf * 32 + lhi * 16)) ^ aswz));
            uint32_t b[4][2];
#pragma unroll
            for (int bf = 0; bf < 2; ++bf)
                ldsm_x4_t(b[bf * 2][0], b[bf * 2][1], b[bf * 2 + 1][0], b[bf * 2 + 1][1],
                          bbase + (uint32_t)(kf * 16) * 256 +
                          (((uint32_t)(wn * 64 + bf * 32 + lhi * 16)) ^ aswz));
#pragma unroll
            for (int nf = 0; nf < 4; ++nf)
                mma_16816(acc[nf][0], acc[nf][1], acc[nf][2], acc[nf][3],
                          a[0], a[1], a[2], a[3], b[nf][0], b[nf][1]);
        }
        __syncthreads();                         // slot consumed

        if (t + DEPTH < NT) issue(t + DEPTH);
        CP_COMMIT();
    }

    // ---- row sums: 8 threads/row (q = lane&7), xor-reduce
    rsum += __shfl_xor_sync(0xFFFFFFFFu, rsum, 1);
    rsum += __shfl_xor_sync(0xFFFFFFFFu, rsum, 2);
    rsum += __shfl_xor_sync(0xFFFFFFFFu, rsum, 4);
    float* srow = (float*)(smem + SROW_OFF);
    if (q == 0) srow[prow] = rsum;
    __syncthreads();

    // ---- epilogue: warp rows wm*16, cols wn*32
    {
        const int rlo = wm * 16 + (lane >> 2);
        const int rhi = rlo + 8;
        const float slo = srow[rlo];
        const float shi = srow[rhi];
        const float invlo = (slo > 0.f) ? (1.f / slo) : 0.f;
        const float invhi = (shi > 0.f) ? (1.f / shi) : 0.f;
        float* outlo = out + (size_t)(i0 + rlo) * OUT_DIM + wn * 32 + (lane & 3) * 2;
        float* outhi = out + (size_t)(i0 + rhi) * OUT_DIM + wn * 32 + (lane & 3) * 2;
#pragma unroll
        for (int nf = 0; nf < 4; ++nf) {
            float2 v;
            v.x = acc[nf][0] * invlo; v.y = acc[nf][1] * invlo;
            *(float2*)(outlo + nf * 8) = v;
            v.x = acc[nf][2] * invhi; v.y = acc[nf][3] * invhi;
            *(float2*)(outhi + nf * 8) = v;
        }
    }
}

// ---------------------------------------------------------------------------
extern "C" void kernel_launch(void* const* d_in, const int* in_sizes, int n_in,
                              void* d_out, int out_size) {
    const float* h   = (const float*)d_in[0];   // [8192,256] f32
    const int*   adj = (const int*)  d_in[1];   // [8192,8192] i32
    const float* W   = (const float*)d_in[2];   // [256,128] f32
    const float* a   = (const float*)d_in[3];   // [256] f32
    float* out = (float*)d_out;                 // [8192,128] f32

    cudaFuncSetAttribute(gat_kernel, cudaFuncAttributeMaxDynamicSharedMemorySize, SMEM_TOT);

    wh_kernel<<<N_NODES / 64, 256>>>(h, W, a);
    gat_kernel<<<N_NODES / RT, 512, SMEM_TOT>>>(adj, out);
}

// round 10
// speedup vs baseline: 8.7298x; 1.0617x over previous
#include <cuda_runtime.h>
#include <cuda_fp16.h>
#include <cstdint>

#define N_NODES 8192
#define IN_DIM  256
#define OUT_DIM 128
#define NEG_SLOPE 0.2f
#define LOG2E 1.4426950408889634f

// ---------------- scratch (no allocations allowed) ----------------
__device__ float  g_ssrc[N_NODES];             // s_src * log2(e)
__device__ float  g_sdst[N_NODES];             // s_dst * log2(e)
__device__ __half g_Whrm[N_NODES * OUT_DIM];   // Wh row-major fp16 [node][feat]

__device__ __forceinline__ uint32_t smem_u32(const void* p) {
    uint32_t a;
    asm("{ .reg .u64 t; cvta.to.shared.u64 t, %1; cvt.u32.u64 %0, t; }" : "=r"(a) : "l"(p));
    return a;
}
__device__ __forceinline__ void cp16(uint32_t dst, const void* src) {
    asm volatile("cp.async.cg.shared.global [%0], [%1], 16;" :: "r"(dst), "l"(src) : "memory");
}
#define CP_COMMIT() asm volatile("cp.async.commit_group;" ::: "memory")
#define CP_WAIT1()  asm volatile("cp.async.wait_group 1;" ::: "memory")
#define CP_WAIT2()  asm volatile("cp.async.wait_group 2;" ::: "memory")

__device__ __forceinline__ float ex2f(float x) {
    float y; asm("ex2.approx.f32 %0, %1;" : "=f"(y) : "f"(x)); return y;
}

__device__ __forceinline__ void ldsm_x4(uint32_t& r0, uint32_t& r1, uint32_t& r2, uint32_t& r3,
                                        uint32_t addr) {
    asm volatile("ldmatrix.sync.aligned.m8n8.x4.shared.b16 {%0,%1,%2,%3}, [%4];"
                 : "=r"(r0), "=r"(r1), "=r"(r2), "=r"(r3) : "r"(addr));
}
__device__ __forceinline__ void ldsm_x4_t(uint32_t& r0, uint32_t& r1, uint32_t& r2, uint32_t& r3,
                                          uint32_t addr) {
    asm volatile("ldmatrix.sync.aligned.m8n8.x4.trans.shared.b16 {%0,%1,%2,%3}, [%4];"
                 : "=r"(r0), "=r"(r1), "=r"(r2), "=r"(r3) : "r"(addr));
}
__device__ __forceinline__ void mma_16816(float& c0, float& c1, float& c2, float& c3,
                                          uint32_t a0, uint32_t a1, uint32_t a2, uint32_t a3,
                                          uint32_t b0, uint32_t b1) {
    asm volatile("mma.sync.aligned.m16n8k16.row.col.f32.f16.f16.f32 "
                 "{%0,%1,%2,%3}, {%4,%5,%6,%7}, {%8,%9}, {%0,%1,%2,%3};"
                 : "+f"(c0), "+f"(c1), "+f"(c2), "+f"(c3)
                 : "r"(a0), "r"(a1), "r"(a2), "r"(a3), "r"(b0), "r"(b1));
}

// ---------------------------------------------------------------------------
// Kernel A: tiled fp32 GEMM. Block = 64 rows, 256 threads.
// ---------------------------------------------------------------------------
__global__ void __launch_bounds__(256) wh_kernel(const float* __restrict__ h,
                                                 const float* __restrict__ W,
                                                 const float* __restrict__ a) {
    __shared__ float hs[64 * 32];      // h chunk  [row][k]
    __shared__ float ws[32 * 128];     // W chunk  [k][col]

    const int r0  = blockIdx.x * 64;
    const int tid = threadIdx.x;
    const int tx  = tid & 31;
    const int ry  = tid >> 5;

    float acc[8][4];
#pragma unroll
    for (int i = 0; i < 8; ++i)
#pragma unroll
        for (int c = 0; c < 4; ++c) acc[i][c] = 0.f;

    for (int ck = 0; ck < 8; ++ck) {
        __syncthreads();
#pragma unroll
        for (int p = 0; p < 2; ++p) {
            const int idx = tid + p * 256;
            const int row = idx >> 3, kq = idx & 7;
            ((float4*)hs)[row * 8 + kq] =
                *(const float4*)(h + (size_t)(r0 + row) * IN_DIM + ck * 32 + kq * 4);
        }
#pragma unroll
        for (int p = 0; p < 4; ++p) {
            const int idx = tid + p * 256;
            const int kr = idx >> 5, cq = idx & 31;
            ((float4*)ws)[kr * 32 + cq] =
                *(const float4*)(W + (size_t)(ck * 32 + kr) * OUT_DIM + cq * 4);
        }
        __syncthreads();
#pragma unroll 4
        for (int kk = 0; kk < 32; ++kk) {
            const float4 wv = ((const float4*)ws)[kk * 32 + tx];
#pragma unroll
            for (int i = 0; i < 8; ++i) {
                const float hv = hs[(ry * 8 + i) * 32 + kk];
                acc[i][0] = fmaf(hv, wv.x, acc[i][0]);
                acc[i][1] = fmaf(hv, wv.y, acc[i][1]);
                acc[i][2] = fmaf(hv, wv.z, acc[i][2]);
                acc[i][3] = fmaf(hv, wv.w, acc[i][3]);
            }
        }
    }

#pragma unroll
    for (int i = 0; i < 8; ++i) {
        const int row = r0 + ry * 8 + i;
        const __half2 lo = __floats2half2_rn(acc[i][0], acc[i][1]);
        const __half2 hi = __floats2half2_rn(acc[i][2], acc[i][3]);
        uint2 v;
        v.x = *(const uint32_t*)&lo;
        v.y = *(const uint32_t*)&hi;
        *(uint2*)(g_Whrm + (size_t)row * OUT_DIM + tx * 4) = v;
    }

    const float4 as4 = *(const float4*)(a + tx * 4);
    const float4 ad4 = *(const float4*)(a + OUT_DIM + tx * 4);
#pragma unroll
    for (int i = 0; i < 8; ++i) {
        float v1 = acc[i][0] * as4.x + acc[i][1] * as4.y + acc[i][2] * as4.z + acc[i][3] * as4.w;
        float v2 = acc[i][0] * ad4.x + acc[i][1] * ad4.y + acc[i][2] * ad4.z + acc[i][3] * ad4.w;
#pragma unroll
        for (int o = 16; o > 0; o >>= 1) {
            v1 += __shfl_xor_sync(0xFFFFFFFFu, v1, o);
            v2 += __shfl_xor_sync(0xFFFFFFFFu, v2, o);
        }
        if (tx == 0) {
            g_ssrc[r0 + ry * 8 + i] = v1 * LOG2E;
            g_sdst[r0 + ry * 8 + i] = v2 * LOG2E;
        }
    }
}

// ---------------------------------------------------------------------------
// Kernel B: fused flash-GAT. Per iteration: MMA(t) || P(t+1), ONE barrier.
// As double-buffered; 3-stage cp.async for adj+Bs. 512 threads, 16 warps.
// ---------------------------------------------------------------------------
#define RT 64
#define KT 64
#define NT (N_NODES / KT)
#define DEPTH 3

#define ADJ_ST(s) ((s) * 16384)            // 3 x 16KB adj stages
#define BS_ST(s)  (49152 + (s) * 16384)    // 3 x 16KB Bs stages (swizzled)
#define AS_OFF(b) (98304 + (b) * 8192)     // 2 x 8KB As buffers (swizzled)
#define SDST_OFF  114688                   // 32KB staged g_sdst
#define SROW_OFF  147456                   // 256B row sums
#define SMEM_TOT  147712

__global__ void __launch_bounds__(512) gat_kernel(const int* __restrict__ adj,
                                                  float* __restrict__ out) {
    extern __shared__ char smem[];
    const uint32_t sb = smem_u32(smem);

    const int tid  = threadIdx.x;
    const int lane = tid & 31;
    const int wid  = tid >> 5;
    const int i0   = blockIdx.x * RT;
    const int wm   = wid & 3;       // rows wm*16
    const int wn   = wid >> 2;      // cols wn*32

    const int prow = tid >> 3;
    const int q    = tid & 7;
    const float si2 = g_ssrc[i0 + prow];
    float rsum = 0.f;

    float acc[4][4];
#pragma unroll
    for (int j = 0; j < 4; ++j)
#pragma unroll
        for (int k = 0; k < 4; ++k) acc[j][k] = 0.f;

    const int l15 = lane & 15;
    const int lhi = lane >> 4;
    const uint32_t aswz   = (uint32_t)((l15 & 7) << 4);
    const uint32_t arowoff = (uint32_t)(wm * 16 + l15) * 128;

    const int* aptr = adj + (size_t)(i0 + prow) * N_NODES + q * 8;
    const uint32_t adj_thr_off = (uint32_t)(prow * 256 + q * 32);
    const uint32_t as_thr_off  = (uint32_t)(prow * 128);

    // ---- stage g_sdst (2048 float4)
    {
        float4* dst = (float4*)(smem + SDST_OFF);
        const float4* src = (const float4*)g_sdst;
#pragma unroll
        for (int r = 0; r < 4; ++r) dst[tid + r * 512] = src[tid + r * 512];
    }

    auto issue = [&](int tt) {
        const int slot = tt % DEPTH;
        const uint32_t ab = sb + ADJ_ST(slot) + adj_thr_off;
        const char* asrc = (const char*)aptr + (size_t)tt * KT * 4;
#pragma unroll
        for (int v = 0; v < 2; ++v) cp16(ab + v * 16, asrc + v * 16);
        const uint32_t bb = sb + BS_ST(slot);
#pragma unroll
        for (int p = 0; p < 2; ++p) {
            const int idx = tid + p * 512;
            const int br = idx >> 4;
            const int bg = idx & 15;
            cp16(bb + br * 256 + ((bg * 16) ^ ((br & 7) << 4)),
                 g_Whrm + (size_t)(tt * KT + br) * OUT_DIM + bg * 8);
        }
    };

    // P-phase: produce As for tile tt into buffer buf
    auto pphase = [&](int tt, int buf) {
        const int slot = tt % DEPTH;
        const char* adjS = smem + ADJ_ST(slot) + adj_thr_off;
        const float* sdS = (const float*)(smem + SDST_OFF) + tt * KT + q * 8;
        char* asD = smem + AS_OFF(buf) + as_thr_off;
#pragma unroll
        for (int v = 0; v < 2; ++v) {
            const int4 av   = *(const int4*)(adjS + v * 16);
            const float4 sj = *(const float4*)(sdS + v * 4);
            float e0 = si2 + sj.x; e0 = fmaxf(e0, NEG_SLOPE * e0);
            float e1 = si2 + sj.y; e1 = fmaxf(e1, NEG_SLOPE * e1);
            float e2 = si2 + sj.z; e2 = fmaxf(e2, NEG_SLOPE * e2);
            float e3 = si2 + sj.w; e3 = fmaxf(e3, NEG_SLOPE * e3);
            float p0 = ex2f(e0); p0 = av.x ? p0 : 0.f;
            float p1 = ex2f(e1); p1 = av.y ? p1 : 0.f;
            float p2 = ex2f(e2); p2 = av.z ? p2 : 0.f;
            float p3 = ex2f(e3); p3 = av.w ? p3 : 0.f;
            rsum += (p0 + p1) + (p2 + p3);
            const __half2 h01 = __floats2half2_rn(p0, p1);
            const __half2 h23 = __floats2half2_rn(p2, p3);
            uint2 pk;
            pk.x = *(const uint32_t*)&h01;
            pk.y = *(const uint32_t*)&h23;
            *(uint2*)(asD + ((q * 16 + v * 8) ^ ((prow & 7) << 4))) = pk;
        }
    };

    // ---- prologue: 3 stages in flight; P(0) into buffer 0
#pragma unroll
    for (int s = 0; s < DEPTH; ++s) { issue(s); CP_COMMIT(); }
    CP_WAIT2();                 // stage 0 landed
    __syncthreads();
    pphase(0, 0);
    __syncthreads();

    int cur = 0;
    for (int t = 0; t < NT; ++t) {
        // ---- MMA(t): As[cur] x Bs slot t
        const uint32_t abase = sb + AS_OFF(cur) + arowoff;
        const uint32_t bbase = sb + BS_ST(t % DEPTH) + (uint32_t)l15 * 256;
#pragma unroll
        for (int kf = 0; kf < 4; ++kf) {
            uint32_t a[4];
            ldsm_x4(a[0], a[1], a[2], a[3],
                    abase + (((uint32_t)(kf * 32 + lhi * 16)) ^ aswz));
            uint32_t b[4][2];
#pragma unroll
            for (int bf = 0; bf < 2; ++bf)
                ldsm_x4_t(b[bf * 2][0], b[bf * 2][1], b[bf * 2 + 1][0], b[bf * 2 + 1][1],
                          bbase + (uint32_t)(kf * 16) * 256 +
                          (((uint32_t)(wn * 64 + bf * 32 + lhi * 16)) ^ aswz));
#pragma unroll
            for (int nf = 0; nf < 4; ++nf)
                mma_16816(acc[nf][0], acc[nf][1], acc[nf][2], acc[nf][3],
                          a[0], a[1], a[2], a[3], b[nf][0], b[nf][1]);
        }

        // ---- P(t+1) into As[cur^1] (independent of MMA(t); overlaps across warps)
        if (t + 1 < NT) {
            CP_WAIT1();         // stage t+1 landed (t+2 may stay in flight)
            pphase(t + 1, cur ^ 1);
        }
        __syncthreads();        // all MMA(t) + P(t+1) complete

        // ---- refill slot (t+3)%3 == t%3 (fully consumed now)
        if (t + DEPTH < NT) issue(t + DEPTH);
        CP_COMMIT();
        cur ^= 1;
    }

    // ---- row sums: 8 threads/row xor-reduce
    rsum += __shfl_xor_sync(0xFFFFFFFFu, rsum, 1);
    rsum += __shfl_xor_sync(0xFFFFFFFFu, rsum, 2);
    rsum += __shfl_xor_sync(0xFFFFFFFFu, rsum, 4);
    float* srow = (float*)(smem + SROW_OFF);
    if (q == 0) srow[prow] = rsum;
    __syncthreads();

    // ---- epilogue
    {
        const int rlo = wm * 16 + (lane >> 2);
        const int rhi = rlo + 8;
        const float slo = srow[rlo];
        const float shi = srow[rhi];
        const float invlo = (slo > 0.f) ? (1.f / slo) : 0.f;
        const float invhi = (shi > 0.f) ? (1.f / shi) : 0.f;
        float* outlo = out + (size_t)(i0 + rlo) * OUT_DIM + wn * 32 + (lane & 3) * 2;
        float* outhi = out + (size_t)(i0 + rhi) * OUT_DIM + wn * 32 + (lane & 3) * 2;
#pragma unroll
        for (int nf = 0; nf < 4; ++nf) {
            float2 v;
            v.x = acc[nf][0] * invlo; v.y = acc[nf][1] * invlo;
            *(float2*)(outlo + nf * 8) = v;
            v.x = acc[nf][2] * invhi; v.y = acc[nf][3] * invhi;
            *(float2*)(outhi + nf * 8) = v;
        }
    }
}

// ---------------------------------------------------------------------------
extern "C" void kernel_launch(void* const* d_in, const int* in_sizes, int n_in,
                              void* d_out, int out_size) {
    const float* h   = (const float*)d_in[0];   // [8192,256] f32
    const int*   adj = (const int*)  d_in[1];   // [8192,8192] i32
    const float* W   = (const float*)d_in[2];   // [256,128] f32
    const float* a   = (const float*)d_in[3];   // [256] f32
    float* out = (float*)d_out;                 // [8192,128] f32

    cudaFuncSetAttribute(gat_kernel, cudaFuncAttributeMaxDynamicSharedMemorySize, SMEM_TOT);

    wh_kernel<<<N_NODES / 64, 256>>>(h, W, a);
    gat_kernel<<<N_NODES / RT, 512, SMEM_TOT>>>(adj, out);
}

// round 11
// speedup vs baseline: 10.0038x; 1.1459x over previous
#include <cuda_runtime.h>
#include <cuda_fp16.h>
#include <cstdint>

#define N_NODES 8192
#define IN_DIM  256
#define OUT_DIM 128
#define NEG_SLOPE 0.2f
#define LOG2E 1.4426950408889634f

// ---------------- scratch (no allocations allowed) ----------------
__device__ float  g_ssrc[N_NODES];             // s_src * log2(e)  (fp32)
__device__ __half g_sdsth[N_NODES];            // s_dst * log2(e)  (fp16)
__device__ __half g_Whrm[N_NODES * OUT_DIM];   // Wh row-major fp16 [node][feat]

__device__ __forceinline__ uint32_t smem_u32(const void* p) {
    uint32_t a;
    asm("{ .reg .u64 t; cvta.to.shared.u64 t, %1; cvt.u32.u64 %0, t; }" : "=r"(a) : "l"(p));
    return a;
}
__device__ __forceinline__ void cp16(uint32_t dst, const void* src) {
    asm volatile("cp.async.cg.shared.global [%0], [%1], 16;" :: "r"(dst), "l"(src) : "memory");
}
#define CP_COMMIT() asm volatile("cp.async.commit_group;" ::: "memory")
#define CP_WAIT2()  asm volatile("cp.async.wait_group 2;" ::: "memory")
#define CP_WAIT3()  asm volatile("cp.async.wait_group 3;" ::: "memory")

__device__ __forceinline__ uint32_t ex2_h2(uint32_t x) {
    uint32_t y; asm("ex2.approx.f16x2 %0, %1;" : "=r"(y) : "r"(x)); return y;
}

__device__ __forceinline__ void ldsm_x4(uint32_t& r0, uint32_t& r1, uint32_t& r2, uint32_t& r3,
                                        uint32_t addr) {
    asm volatile("ldmatrix.sync.aligned.m8n8.x4.shared.b16 {%0,%1,%2,%3}, [%4];"
                 : "=r"(r0), "=r"(r1), "=r"(r2), "=r"(r3) : "r"(addr));
}
__device__ __forceinline__ void ldsm_x4_t(uint32_t& r0, uint32_t& r1, uint32_t& r2, uint32_t& r3,
                                          uint32_t addr) {
    asm volatile("ldmatrix.sync.aligned.m8n8.x4.trans.shared.b16 {%0,%1,%2,%3}, [%4];"
                 : "=r"(r0), "=r"(r1), "=r"(r2), "=r"(r3) : "r"(addr));
}
__device__ __forceinline__ void mma_16816(float& c0, float& c1, float& c2, float& c3,
                                          uint32_t a0, uint32_t a1, uint32_t a2, uint32_t a3,
                                          uint32_t b0, uint32_t b1) {
    asm volatile("mma.sync.aligned.m16n8k16.row.col.f32.f16.f16.f32 "
                 "{%0,%1,%2,%3}, {%4,%5,%6,%7}, {%8,%9}, {%0,%1,%2,%3};"
                 : "+f"(c0), "+f"(c1), "+f"(c2), "+f"(c3)
                 : "r"(a0), "r"(a1), "r"(a2), "r"(a3), "r"(b0), "r"(b1));
}

// ---------------------------------------------------------------------------
// Kernel A: tiled fp32 GEMM. Block = 64 rows, 256 threads.
// ---------------------------------------------------------------------------
__global__ void __launch_bounds__(256) wh_kernel(const float* __restrict__ h,
                                                 const float* __restrict__ W,
                                                 const float* __restrict__ a) {
    __shared__ float hs[64 * 32];
    __shared__ float ws[32 * 128];

    const int r0  = blockIdx.x * 64;
    const int tid = threadIdx.x;
    const int tx  = tid & 31;
    const int ry  = tid >> 5;

    float acc[8][4];
#pragma unroll
    for (int i = 0; i < 8; ++i)
#pragma unroll
        for (int c = 0; c < 4; ++c) acc[i][c] = 0.f;

    for (int ck = 0; ck < 8; ++ck) {
        __syncthreads();
#pragma unroll
        for (int p = 0; p < 2; ++p) {
            const int idx = tid + p * 256;
            const int row = idx >> 3, kq = idx & 7;
            ((float4*)hs)[row * 8 + kq] =
                *(const float4*)(h + (size_t)(r0 + row) * IN_DIM + ck * 32 + kq * 4);
        }
#pragma unroll
        for (int p = 0; p < 4; ++p) {
            const int idx = tid + p * 256;
            const int kr = idx >> 5, cq = idx & 31;
            ((float4*)ws)[kr * 32 + cq] =
                *(const float4*)(W + (size_t)(ck * 32 + kr) * OUT_DIM + cq * 4);
        }
        __syncthreads();
#pragma unroll 4
        for (int kk = 0; kk < 32; ++kk) {
            const float4 wv = ((const float4*)ws)[kk * 32 + tx];
#pragma unroll
            for (int i = 0; i < 8; ++i) {
                const float hv = hs[(ry * 8 + i) * 32 + kk];
                acc[i][0] = fmaf(hv, wv.x, acc[i][0]);
                acc[i][1] = fmaf(hv, wv.y, acc[i][1]);
                acc[i][2] = fmaf(hv, wv.z, acc[i][2]);
                acc[i][3] = fmaf(hv, wv.w, acc[i][3]);
            }
        }
    }

#pragma unroll
    for (int i = 0; i < 8; ++i) {
        const int row = r0 + ry * 8 + i;
        const __half2 lo = __floats2half2_rn(acc[i][0], acc[i][1]);
        const __half2 hi = __floats2half2_rn(acc[i][2], acc[i][3]);
        uint2 v;
        v.x = *(const uint32_t*)&lo;
        v.y = *(const uint32_t*)&hi;
        *(uint2*)(g_Whrm + (size_t)row * OUT_DIM + tx * 4) = v;
    }

    const float4 as4 = *(const float4*)(a + tx * 4);
    const float4 ad4 = *(const float4*)(a + OUT_DIM + tx * 4);
#pragma unroll
    for (int i = 0; i < 8; ++i) {
        float v1 = acc[i][0] * as4.x + acc[i][1] * as4.y + acc[i][2] * as4.z + acc[i][3] * as4.w;
        float v2 = acc[i][0] * ad4.x + acc[i][1] * ad4.y + acc[i][2] * ad4.z + acc[i][3] * ad4.w;
#pragma unroll
        for (int o = 16; o > 0; o >>= 1) {
            v1 += __shfl_xor_sync(0xFFFFFFFFu, v1, o);
            v2 += __shfl_xor_sync(0xFFFFFFFFu, v2, o);
        }
        if (tx == 0) {
            g_ssrc[r0 + ry * 8 + i]  = v1 * LOG2E;
            g_sdsth[r0 + ry * 8 + i] = __float2half(v2 * LOG2E);
        }
    }
}

// ---------------------------------------------------------------------------
// Kernel B: fused flash-GAT. half2 P-phase, ones-column MMA row sums,
// 4-stage cp.async (adj + Bs + sdst), one barrier per tile. 512 threads.
// ---------------------------------------------------------------------------
#define RT 64
#define KT 64
#define NT (N_NODES / KT)
#define DEPTH 4

#define ADJ_ST(s) ((s) * 16384)             // 4 x 16KB adj
#define BS_ST(s)  (65536 + (s) * 16384)     // 4 x 16KB Bs (swizzled)
#define AS_OFF(b) (131072 + (b) * 8192)     // 2 x 8KB As (swizzled)
#define SD_ST(s)  (147456 + (s) * 128)      // 4 x 128B sdst (fp16)
#define SROW_OFF  147968                    // 256B row sums
#define SMEM_TOT  148224

#define ONES2 0x3C003C00u

__global__ void __launch_bounds__(512) gat_kernel(const int* __restrict__ adj,
                                                  float* __restrict__ out) {
    extern __shared__ char smem[];
    const uint32_t sb = smem_u32(smem);

    const int tid  = threadIdx.x;
    const int lane = tid & 31;
    const int wid  = tid >> 5;
    const int i0   = blockIdx.x * RT;
    const int wm   = wid & 3;       // rows wm*16
    const int wn   = wid >> 2;      // cols wn*32

    const int prow = tid >> 3;      // 0..63
    const int q    = tid & 7;       // 8 j's at q*8
    const __half2 si2h   = __half2half2(__float2half(g_ssrc[i0 + prow]));
    const __half2 slope2 = __float2half2_rn(NEG_SLOPE);

    float acc[4][4];
#pragma unroll
    for (int j = 0; j < 4; ++j)
#pragma unroll
        for (int k = 0; k < 4; ++k) acc[j][k] = 0.f;
    float accR[4] = {0.f, 0.f, 0.f, 0.f};   // ones-column row sums (wn==0 warps)

    const int l15 = lane & 15;
    const int lhi = lane >> 4;
    const uint32_t aswz    = (uint32_t)((l15 & 7) << 4);
    const uint32_t arowoff = (uint32_t)(wm * 16 + l15) * 128;

    const int* aptr = adj + (size_t)(i0 + prow) * N_NODES + q * 8;
    const uint32_t adj_thr_off = (uint32_t)(prow * 256 + q * 32);
    const uint32_t as_thr_off  = (uint32_t)(prow * 128);

    auto issue = [&](int tt) {
        const int slot = tt % DEPTH;
        const uint32_t ab = sb + ADJ_ST(slot) + adj_thr_off;
        const char* asrc = (const char*)aptr + (size_t)tt * KT * 4;
#pragma unroll
        for (int v = 0; v < 2; ++v) cp16(ab + v * 16, asrc + v * 16);
        const uint32_t bb = sb + BS_ST(slot);
#pragma unroll
        for (int p = 0; p < 2; ++p) {
            const int idx = tid + p * 512;
            const int br = idx >> 4;
            const int bg = idx & 15;
            cp16(bb + br * 256 + ((bg * 16) ^ ((br & 7) << 4)),
                 g_Whrm + (size_t)(tt * KT + br) * OUT_DIM + bg * 8);
        }
        if (tid < 8)
            cp16(sb + SD_ST(slot) + tid * 16, g_sdsth + tt * KT + tid * 8);
    };

    // P-phase: produce As tile tt into buffer buf (all half2)
    auto pphase = [&](int tt, int buf) {
        const int slot = tt % DEPTH;
        const char* adjS = smem + ADJ_ST(slot) + adj_thr_off;
        const int4 av0 = *(const int4*)(adjS);
        const int4 av1 = *(const int4*)(adjS + 16);
        const uint4 sjp = *(const uint4*)(smem + SD_ST(slot) + q * 16);
        const uint32_t sjv[4] = {sjp.x, sjp.y, sjp.z, sjp.w};
        const int ae[4] = {av0.x, av0.y, av0.z, av0.w};
        const int ao[4] = {av1.x, av1.y, av1.z, av1.w};
        // element pairs: i=0 ->(av0.x,av0.y), 1 ->(av0.z,av0.w), 2 ->(av1.x,av1.y), 3 ->(av1.z,av1.w)
        uint32_t outv[4];
#pragma unroll
        for (int i = 0; i < 4; ++i) {
            const __half2 sj = *(const __half2*)&sjv[i];
            __half2 e  = __hadd2(si2h, sj);
            e = __hmax2(e, __hmul2(e, slope2));
            uint32_t p = ex2_h2(*(const uint32_t*)&e);
            const int m0 = (i < 2) ? ((i == 0) ? av0.x : av0.z) : ((i == 2) ? av1.x : av1.z);
            const int m1 = (i < 2) ? ((i == 0) ? av0.y : av0.w) : ((i == 2) ? av1.y : av1.w);
            const uint32_t mask = (uint32_t)(m0 | (m1 << 16)) * 0x3C00u;
            const __half2 ph = __hmul2(*(const __half2*)&p, *(const __half2*)&mask);
            outv[i] = *(const uint32_t*)&ph;
        }
        uint4 st; st.x = outv[0]; st.y = outv[1]; st.z = outv[2]; st.w = outv[3];
        *(uint4*)(smem + AS_OFF(buf) + as_thr_off + ((q * 16) ^ ((prow & 7) << 4))) = st;
    };

    // ---- prologue: 4 stages in flight; P(0) into buffer 0
#pragma unroll
    for (int s = 0; s < DEPTH; ++s) { issue(s); CP_COMMIT(); }
    CP_WAIT3();                 // stage 0 landed
    __syncthreads();
    pphase(0, 0);
    __syncthreads();

    int cur = 0;
    for (int t = 0; t < NT; ++t) {
        // ---- MMA(t): As[cur] x Bs slot t
        const uint32_t abase = sb + AS_OFF(cur) + arowoff;
        const uint32_t bbase = sb + BS_ST(t % DEPTH) + (uint32_t)l15 * 256;
#pragma unroll
        for (int kf = 0; kf < 4; ++kf) {
            uint32_t a[4];
            ldsm_x4(a[0], a[1], a[2], a[3],
                    abase + (((uint32_t)(kf * 32 + lhi * 16)) ^ aswz));
            uint32_t b[4][2];
#pragma unroll
            for (int bf = 0; bf < 2; ++bf)
                ldsm_x4_t(b[bf * 2][0], b[bf * 2][1], b[bf * 2 + 1][0], b[bf * 2 + 1][1],
                          bbase + (uint32_t)(kf * 16) * 256 +
                          (((uint32_t)(wn * 64 + bf * 32 + lhi * 16)) ^ aswz));
#pragma unroll
            for (int nf = 0; nf < 4; ++nf)
                mma_16816(acc[nf][0], acc[nf][1], acc[nf][2], acc[nf][3],
                          a[0], a[1], a[2], a[3], b[nf][0], b[nf][1]);
            if (wn == 0)   // ones-column MMA -> row sums on tensor pipe
                mma_16816(accR[0], accR[1], accR[2], accR[3],
                          a[0], a[1], a[2], a[3], ONES2, ONES2);
        }

        // ---- P(t+1) into As[cur^1]
        if (t + 1 < NT) {
            CP_WAIT2();         // stage t+1 landed
            pphase(t + 1, cur ^ 1);
        }
        __syncthreads();

        if (t + DEPTH < NT) issue(t + DEPTH);
        CP_COMMIT();
        cur ^= 1;
    }

    // ---- row sums from ones-MMA (wn==0 warps; cols duplicated -> use c0/c2)
    float* srow = (float*)(smem + SROW_OFF);
    if (wn == 0 && (lane & 3) == 0) {
        const int r = wm * 16 + (lane >> 2);
        srow[r]     = accR[0];
        srow[r + 8] = accR[2];
    }
    __syncthreads();

    // ---- epilogue
    {
        const int rlo = wm * 16 + (lane >> 2);
        const int rhi = rlo + 8;
        const float slo = srow[rlo];
        const float shi = srow[rhi];
        const float invlo = (slo > 0.f) ? (1.f / slo) : 0.f;
        const float invhi = (shi > 0.f) ? (1.f / shi) : 0.f;
        float* outlo = out + (size_t)(i0 + rlo) * OUT_DIM + wn * 32 + (lane & 3) * 2;
        float* outhi = out + (size_t)(i0 + rhi) * OUT_DIM + wn * 32 + (lane & 3) * 2;
#pragma unroll
        for (int nf = 0; nf < 4; ++nf) {
            float2 v;
            v.x = acc[nf][0] * invlo; v.y = acc[nf][1] * invlo;
            *(float2*)(outlo + nf * 8) = v;
            v.x = acc[nf][2] * invhi; v.y = acc[nf][3] * invhi;
            *(float2*)(outhi + nf * 8) = v;
        }
    }
}

// ---------------------------------------------------------------------------
extern "C" void kernel_launch(void* const* d_in, const int* in_sizes, int n_in,
                              void* d_out, int out_size) {
    const float* h   = (const float*)d_in[0];   // [8192,256] f32
    const int*   adj = (const int*)  d_in[1];   // [8192,8192] i32
    const float* W   = (const float*)d_in[2];   // [256,128] f32
    const float* a   = (const float*)d_in[3];   // [256] f32
    float* out = (float*)d_out;                 // [8192,128] f32

    cudaFuncSetAttribute(gat_kernel, cudaFuncAttributeMaxDynamicSharedMemorySize, SMEM_TOT);

    wh_kernel<<<N_NODES / 64, 256>>>(h, W, a);
    gat_kernel<<<N_NODES / RT, 512, SMEM_TOT>>>(adj, out);
}